// round 1
// baseline (speedup 1.0000x reference)
#include <cuda_runtime.h>
#include <math.h>

#define TT 64
#define BATCH 32
#define POS_V 48
#define WORD_V 32000
#define P_EMB 128
#define W_EMB 512
#define P_HID 256
#define W_HID 1024

// ---------------- scratch (static device memory; no allocs) ----------------
// layout (floats):
//  ph[2]   : 2 * 32*256   = 16384
//  pc      : 32*256       = 8192
//  wh0[2]  : 2 * 32*1024  = 65536
//  wc0     : 32*1024      = 32768
//  wh1[2]  : 2 * 32*1024  = 65536
//  wc1     : 32*1024      = 32768
//  lastw   : 32*1024      = 32768
//  lastp   : 32*256       = 8192
//  e       : 32*512       = 16384
#define OFF_PH0   0
#define OFF_PH1   8192
#define OFF_PC    16384
#define OFF_WH0A  24576
#define OFF_WH0B  57344
#define OFF_WC0   90112
#define OFF_WH1A  122880
#define OFF_WH1B  155648
#define OFF_WC1   188416
#define OFF_LASTW 221184
#define OFF_LASTP 253952
#define OFF_E     262144
#define SCRATCH_TOTAL 278528

__device__ __align__(256) float g_scratch[SCRATCH_TOTAL];

// ---------------- zero init ----------------
__global__ void k_zero(float* __restrict__ s) {
    int i = blockIdx.x * 256 + threadIdx.x;     // total SCRATCH_TOTAL/4 float4s
    ((float4*)s)[i] = make_float4(0.f, 0.f, 0.f, 0.f);
}

// ---------------- generic 32-row projection: out = act(X @ W^T + b) ----------------
// X [32,K] row-major, W [N,K] row-major. JT columns per block, 256 threads.
template<int JT, int ACT>  // ACT: 0 = none, 1 = tanh
__global__ void k_proj(const float* __restrict__ X, int K,
                       const float* __restrict__ W,
                       const float* __restrict__ bias,
                       float* __restrict__ out, int N)
{
    constexpr int OPT  = (32 * JT) / 256;  // rows (outputs) per thread
    constexpr int KQ   = 16;               // float4s per 64-float chunk
    constexpr int LDS4 = 17;               // padded row stride (float4s)
    __shared__ float4 Xs[32 * LDS4];
    __shared__ float4 Ws[JT * LDS4];

    int tid = threadIdx.x;
    int jj  = tid % JT;
    int rg  = tid / JT;
    int j   = blockIdx.x * JT + jj;

    float b = bias ? bias[j] : 0.f;
    float acc[OPT];
#pragma unroll
    for (int i = 0; i < OPT; i++) acc[i] = b;

    for (int k0 = 0; k0 < K; k0 += 64) {
        for (int i = tid; i < 32 * KQ; i += 256) {
            int r = i >> 4, kq = i & 15;
            Xs[r * LDS4 + kq] = *(const float4*)(X + (size_t)r * K + k0 + kq * 4);
        }
        for (int i = tid; i < JT * KQ; i += 256) {
            int rr = i >> 4, kq = i & 15;
            Ws[rr * LDS4 + kq] =
                *(const float4*)(W + (size_t)(blockIdx.x * JT + rr) * K + k0 + kq * 4);
        }
        __syncthreads();
#pragma unroll
        for (int kq = 0; kq < KQ; kq++) {
            float4 wv = Ws[jj * LDS4 + kq];
#pragma unroll
            for (int i = 0; i < OPT; i++) {
                float4 xv = Xs[(rg * OPT + i) * LDS4 + kq];
                acc[i] = fmaf(xv.x, wv.x, acc[i]);
                acc[i] = fmaf(xv.y, wv.y, acc[i]);
                acc[i] = fmaf(xv.z, wv.z, acc[i]);
                acc[i] = fmaf(xv.w, wv.w, acc[i]);
            }
        }
        __syncthreads();
    }
#pragma unroll
    for (int i = 0; i < OPT; i++) {
        float v = acc[i];
        if (ACT == 1) v = tanhf(v);
        out[(size_t)(rg * OPT + i) * N + j] = v;
    }
}

// ---------------- fused LSTM cell ----------------
// gates = [X0|X1] @ Wih^T + Hold @ Whh^T + bih + bhh  (PyTorch i,f,g,o order)
// Each block computes JT hidden units (all 4 gates, all 32 rows) and does the
// cell update in-kernel. blockDim = 32*JT. Grid = H/JT.
// If idx != nullptr, X0 is an embedding table gathered with idx (row r -> idx[r]).
template<int JT>
__global__ void k_lstm(
    const int*   __restrict__ idx,
    const float* __restrict__ X0, int K0,
    const float* __restrict__ X1, int K1,
    const float* __restrict__ Hold, int KH,
    const float* __restrict__ Wih, const float* __restrict__ Whh,
    const float* __restrict__ bih, const float* __restrict__ bhh,
    float* __restrict__ Hnew, float* __restrict__ C, int H)
{
    constexpr int NT   = 32 * JT;
    constexpr int KQ   = 16;
    constexpr int LDS4 = 17;
    __shared__ float4 Xs[32 * LDS4];
    __shared__ float4 Ws[4 * JT * LDS4];
    __shared__ const float* rp[32];

    int tid = threadIdx.x;
    int jj  = tid % JT;
    int r   = tid / JT;
    int j   = blockIdx.x * JT + jj;

    float acc[4];
#pragma unroll
    for (int g = 0; g < 4; g++) acc[g] = bih[g * H + j] + bhh[g * H + j];

    for (int seg = 0; seg < 3; seg++) {
        const float* Wb; const float* Xb; int K, ld, cb; bool gather = false;
        if (seg == 0)      { Xb = X0;   K = K0; Wb = Wih; ld = K0 + K1; cb = 0;  gather = (idx != nullptr); }
        else if (seg == 1) { Xb = X1;   K = K1; Wb = Wih; ld = K0 + K1; cb = K0; }
        else               { Xb = Hold; K = KH; Wb = Whh; ld = KH;      cb = 0;  }
        if (K == 0) continue;

        if (tid < 32) rp[tid] = gather ? (X0 + (size_t)idx[tid] * K0)
                                       : (Xb + (size_t)tid * K);
        __syncthreads();

        for (int k0 = 0; k0 < K; k0 += 64) {
            for (int i = tid; i < 32 * KQ; i += NT) {
                int rr = i >> 4, kq = i & 15;
                Xs[rr * LDS4 + kq] = *(const float4*)(rp[rr] + k0 + kq * 4);
            }
            for (int i = tid; i < 4 * JT * KQ; i += NT) {
                int rr = i >> 4, kq = i & 15;
                int g = rr / JT, u = rr % JT;
                Ws[rr * LDS4 + kq] =
                    *(const float4*)(Wb + (size_t)(g * H + blockIdx.x * JT + u) * ld + cb + k0 + kq * 4);
            }
            __syncthreads();
#pragma unroll
            for (int kq = 0; kq < KQ; kq++) {
                float4 xv = Xs[r * LDS4 + kq];
#pragma unroll
                for (int g = 0; g < 4; g++) {
                    float4 wv = Ws[(g * JT + jj) * LDS4 + kq];
                    acc[g] = fmaf(xv.x, wv.x, acc[g]);
                    acc[g] = fmaf(xv.y, wv.y, acc[g]);
                    acc[g] = fmaf(xv.z, wv.z, acc[g]);
                    acc[g] = fmaf(xv.w, wv.w, acc[g]);
                }
            }
            __syncthreads();
        }
    }

    float iv = 1.f / (1.f + expf(-acc[0]));
    float fv = 1.f / (1.f + expf(-acc[1]));
    float gv = tanhf(acc[2]);
    float ov = 1.f / (1.f + expf(-acc[3]));
    float c  = fv * C[(size_t)r * H + j] + iv * gv;
    C[(size_t)r * H + j]    = c;
    Hnew[(size_t)r * H + j] = ov * tanhf(c);
}

// ---------------- pos head: logits + log_softmax (48-way) ----------------
__global__ void k_pos_out(const float* __restrict__ ph, const float* __restrict__ W,
                          const float* __restrict__ bias, float* __restrict__ out)
{
    int r = blockIdx.x;       // row 0..31
    int j = threadIdx.x;      // 64 threads, j<48 active
    __shared__ float vals[48];
    __shared__ float s_lse;
    float v = 0.f;
    if (j < 48) {
        v = bias[j];
        const float4* xp = (const float4*)(ph + r * 256);
        const float4* wp = (const float4*)(W + j * 256);
#pragma unroll 8
        for (int k = 0; k < 64; k++) {
            float4 x = xp[k], w = wp[k];
            v = fmaf(x.x, w.x, v); v = fmaf(x.y, w.y, v);
            v = fmaf(x.z, w.z, v); v = fmaf(x.w, w.w, v);
        }
        vals[j] = v;
    }
    __syncthreads();
    if (threadIdx.x == 0) {
        float m = -1e30f;
        for (int k = 0; k < 48; k++) m = fmaxf(m, vals[k]);
        float s = 0.f;
        for (int k = 0; k < 48; k++) s += expf(vals[k] - m);
        s_lse = m + logf(s);
    }
    __syncthreads();
    if (j < 48) out[r * 48 + j] = v - s_lse;
}

// ---------------- final word log_softmax over all T*B rows ----------------
__global__ void k_wnorm(float* __restrict__ wout)
{
    float* p = wout + (size_t)blockIdx.x * WORD_V;
    __shared__ float red[256];
    int tid = threadIdx.x;

    float m = -1e30f;
    for (int k = tid; k < WORD_V; k += 256) m = fmaxf(m, p[k]);
    red[tid] = m; __syncthreads();
    for (int s = 128; s > 0; s >>= 1) { if (tid < s) red[tid] = fmaxf(red[tid], red[tid + s]); __syncthreads(); }
    m = red[0]; __syncthreads();

    float s = 0.f;
    for (int k = tid; k < WORD_V; k += 256) s += expf(p[k] - m);
    red[tid] = s; __syncthreads();
    for (int st = 128; st > 0; st >>= 1) { if (tid < st) red[tid] += red[tid + st]; __syncthreads(); }
    float lse = m + logf(red[0]);

    for (int k = tid; k < WORD_V; k += 256) p[k] -= lse;
}

// ---------------- launch ----------------
extern "C" void kernel_launch(void* const* d_in, const int* in_sizes, int n_in,
                              void* d_out, int out_size)
{
    const int*   pos          = (const int*)  d_in[0];
    const int*   word         = (const int*)  d_in[1];
    const float* pos_emb_W    = (const float*)d_in[2];
    const float* word_emb_W   = (const float*)d_in[3];
    const float* w2p_W        = (const float*)d_in[4];
    const float* w2p_b        = (const float*)d_in[5];
    const float* p2w_W        = (const float*)d_in[6];
    const float* p2w_b        = (const float*)d_in[7];
    const float* p_Wih0       = (const float*)d_in[8];
    const float* p_Whh0       = (const float*)d_in[9];
    const float* p_bih0       = (const float*)d_in[10];
    const float* p_bhh0       = (const float*)d_in[11];
    const float* w_Wih0       = (const float*)d_in[12];
    const float* w_Whh0       = (const float*)d_in[13];
    const float* w_bih0       = (const float*)d_in[14];
    const float* w_bhh0       = (const float*)d_in[15];
    const float* w_Wih1       = (const float*)d_in[16];
    const float* w_Whh1       = (const float*)d_in[17];
    const float* w_bih1       = (const float*)d_in[18];
    const float* w_bhh1       = (const float*)d_in[19];
    const float* pos_proj_W   = (const float*)d_in[20];
    const float* pos_proj_b   = (const float*)d_in[21];
    const float* word_proj1_W = (const float*)d_in[22];
    const float* word_proj1_b = (const float*)d_in[23];
    const float* word_proj2_b = (const float*)d_in[24];

    float* scratch = nullptr;
    cudaGetSymbolAddress((void**)&scratch, g_scratch);

    float* ph[2]  = { scratch + OFF_PH0,  scratch + OFF_PH1  };
    float* pc     =   scratch + OFF_PC;
    float* wh0[2] = { scratch + OFF_WH0A, scratch + OFF_WH0B };
    float* wc0    =   scratch + OFF_WC0;
    float* wh1[2] = { scratch + OFF_WH1A, scratch + OFF_WH1B };
    float* wc1    =   scratch + OFF_WC1;
    float* lastw  =   scratch + OFF_LASTW;
    float* lastp  =   scratch + OFF_LASTP;
    float* ebuf   =   scratch + OFF_E;

    float* pout = (float*)d_out;
    float* wout = pout + (size_t)TT * BATCH * POS_V;

    k_zero<<<SCRATCH_TOTAL / 4 / 256, 256>>>(scratch);

    for (int t = 0; t < TT; t++) {
        int cur = t & 1, nxt = cur ^ 1;

        // last_w = tanh(w_h1_old @ w2p^T + b)
        k_proj<8, 1><<<W_HID / 8, 256>>>(wh1[cur], W_HID, w2p_W, w2p_b, lastw, W_HID);

        // POS LSTM: x = [p_emb_t, last_w]
        k_lstm<4><<<P_HID / 4, 128>>>(pos + t * BATCH, pos_emb_W, P_EMB,
                                      lastw, W_HID, ph[cur], P_HID,
                                      p_Wih0, p_Whh0, p_bih0, p_bhh0,
                                      ph[nxt], pc, P_HID);

        // last_p = tanh(p_h_new @ p2w^T + b)
        k_proj<8, 1><<<P_HID / 8, 256>>>(ph[nxt], P_HID, p2w_W, p2w_b, lastp, P_HID);

        // pos logits + log_softmax
        k_pos_out<<<BATCH, 64>>>(ph[nxt], pos_proj_W, pos_proj_b,
                                 pout + (size_t)t * BATCH * POS_V);

        // word LSTM layer 0: x = [w_emb_t, last_p]
        k_lstm<8><<<W_HID / 8, 256>>>(word + t * BATCH, word_emb_W, W_EMB,
                                      lastp, P_HID, wh0[cur], W_HID,
                                      w_Wih0, w_Whh0, w_bih0, w_bhh0,
                                      wh0[nxt], wc0, W_HID);

        // word LSTM layer 1: x = w_h0_new
        k_lstm<8><<<W_HID / 8, 256>>>(nullptr, wh0[nxt], W_HID,
                                      nullptr, 0, wh1[cur], W_HID,
                                      w_Wih1, w_Whh1, w_bih1, w_bhh1,
                                      wh1[nxt], wc1, W_HID);

        // e = w_h1_new @ proj1^T + b
        k_proj<8, 0><<<W_EMB / 8, 256>>>(wh1[nxt], W_HID, word_proj1_W, word_proj1_b,
                                         ebuf, W_EMB);

        // word logits (raw) into output buffer
        k_proj<32, 0><<<WORD_V / 32, 256>>>(ebuf, W_EMB, word_emb_W, word_proj2_b,
                                            wout + (size_t)t * BATCH * WORD_V, WORD_V);
    }

    // single final log_softmax pass over all word logits
    k_wnorm<<<TT * BATCH, 256>>>(wout);
}

// round 3
// speedup vs baseline: 1.5522x; 1.5522x over previous
#include <cuda_runtime.h>
#include <math.h>

#define TT 64
#define BATCH 32
#define POS_V 48
#define WORD_V 32000
#define P_EMB 128
#define W_EMB 512
#define P_HID 256
#define W_HID 1024

// ---------------- scratch (static device memory; no allocs) ----------------
#define OFF_PH0   0
#define OFF_PH1   8192
#define OFF_PC    16384
#define OFF_WH0A  24576
#define OFF_WH0B  57344
#define OFF_WC0   90112
#define OFF_WH1A  122880
#define OFF_WH1B  155648
#define OFF_WC1   188416
#define STATE_TOTAL 221184
#define OFF_LASTW 221184
#define OFF_LASTP 253952
#define OFF_EBUF  262144
#define OFF_PBUF  1310720
#define SCRATCH_TOTAL 1835008

__device__ __align__(256) float g_scratch[SCRATCH_TOTAL];

// ---------------- zero init (states only) ----------------
__global__ void k_zero(float* __restrict__ s) {
    int i = blockIdx.x * 256 + threadIdx.x;   // STATE_TOTAL/4 float4s = 55296
    ((float4*)s)[i] = make_float4(0.f, 0.f, 0.f, 0.f);
}

// ---------------- split-K GEMM for M=32: partial[ks] = X @ W^T ----------------
// X = concat([X0(gather?)|X1|Hold]) along K; W rows per col:
//   LSTM: col (global) = u*4+g  -> Wih/Whh row g*H+u   (gate-interleaved layout)
//   proj: col = n               -> W row n
// Block: CB=64 cols, 128 threads, thread = 4 rows x 4 cols. grid=(ncols/CB, KSPLIT).
template<int CB, bool LSTM>
__global__ void k_gemm(const int* __restrict__ idx,
                       const float* __restrict__ X0, int K0,
                       const float* __restrict__ X1, int K1,
                       const float* __restrict__ Hold, int KH,
                       const float* __restrict__ Wih, const float* __restrict__ Whh,
                       float* __restrict__ pbuf, int H, int Nstride, int kchunk)
{
    constexpr int NT = (CB / 4) * 8;       // 128 threads for CB=64
    __shared__ float Xs[32][36];           // [k][m] transposed
    __shared__ float Ws[32][CB + 4];       // [k][c] transposed
    __shared__ const float* rp[32];

    int tid = threadIdx.x;
    int cg = tid % (CB / 4);
    int rg = tid / (CB / 4);

    float acc[4][4];
#pragma unroll
    for (int r = 0; r < 4; r++)
#pragma unroll
        for (int c = 0; c < 4; c++) acc[r][c] = 0.f;

    int kbeg = blockIdx.y * kchunk, kend = kbeg + kchunk;
    int base = 0;
    for (int seg = 0; seg < 3; seg++) {
        const float* Xb; const float* Wb; int K, ld, cb; bool gather = false;
        if (seg == 0)      { Xb = X0;   K = K0; Wb = Wih; ld = K0 + K1; cb = 0;  gather = (idx != nullptr); }
        else if (seg == 1) { Xb = X1;   K = K1; Wb = Wih; ld = K0 + K1; cb = K0; }
        else               { Xb = Hold; K = KH; Wb = Whh; ld = KH;      cb = 0;  }
        int lo = kbeg > base ? kbeg : base;
        int hi = kend < base + K ? kend : base + K;
        if (lo < hi) {
            if (tid < 32) rp[tid] = gather ? (X0 + (size_t)idx[tid] * K0)
                                           : (Xb + (size_t)tid * K);
            __syncthreads();
            for (int k0 = lo; k0 < hi; k0 += 32) {
                int xoff = k0 - base;
#pragma unroll
                for (int i = tid; i < 256; i += NT) {
                    int m = i >> 3, kq = i & 7;
                    float4 v = *(const float4*)(rp[m] + xoff + kq * 4);
                    Xs[kq*4+0][m] = v.x; Xs[kq*4+1][m] = v.y;
                    Xs[kq*4+2][m] = v.z; Xs[kq*4+3][m] = v.w;
                }
#pragma unroll
                for (int i = tid; i < CB * 8; i += NT) {
                    int c = i >> 3, kq = i & 7;
                    int wr;
                    if (LSTM) wr = (c & 3) * H + blockIdx.x * (CB / 4) + (c >> 2);
                    else      wr = blockIdx.x * CB + c;
                    float4 v = *(const float4*)(Wb + (size_t)wr * ld + cb + xoff + kq * 4);
                    Ws[kq*4+0][c] = v.x; Ws[kq*4+1][c] = v.y;
                    Ws[kq*4+2][c] = v.z; Ws[kq*4+3][c] = v.w;
                }
                __syncthreads();
#pragma unroll
                for (int k = 0; k < 32; k++) {
                    float4 a = *(const float4*)&Xs[k][rg * 4];
                    float4 b = *(const float4*)&Ws[k][cg * 4];
                    acc[0][0] = fmaf(a.x, b.x, acc[0][0]);
                    acc[0][1] = fmaf(a.x, b.y, acc[0][1]);
                    acc[0][2] = fmaf(a.x, b.z, acc[0][2]);
                    acc[0][3] = fmaf(a.x, b.w, acc[0][3]);
                    acc[1][0] = fmaf(a.y, b.x, acc[1][0]);
                    acc[1][1] = fmaf(a.y, b.y, acc[1][1]);
                    acc[1][2] = fmaf(a.y, b.z, acc[1][2]);
                    acc[1][3] = fmaf(a.y, b.w, acc[1][3]);
                    acc[2][0] = fmaf(a.z, b.x, acc[2][0]);
                    acc[2][1] = fmaf(a.z, b.y, acc[2][1]);
                    acc[2][2] = fmaf(a.z, b.z, acc[2][2]);
                    acc[2][3] = fmaf(a.z, b.w, acc[2][3]);
                    acc[3][0] = fmaf(a.w, b.x, acc[3][0]);
                    acc[3][1] = fmaf(a.w, b.y, acc[3][1]);
                    acc[3][2] = fmaf(a.w, b.z, acc[3][2]);
                    acc[3][3] = fmaf(a.w, b.w, acc[3][3]);
                }
                __syncthreads();
            }
        }
        base += K;
    }
#pragma unroll
    for (int r = 0; r < 4; r++) {
        float4 v = make_float4(acc[r][0], acc[r][1], acc[r][2], acc[r][3]);
        *(float4*)&pbuf[(size_t)(blockIdx.y * 32 + rg * 4 + r) * Nstride
                        + blockIdx.x * CB + cg * 4] = v;
    }
}

// ---------------- LSTM epilogue: sum partials + bias, cell update ----------------
__global__ void k_lstm_epi(const float* __restrict__ pbuf, int ksplit,
                           const float* __restrict__ bih, const float* __restrict__ bhh,
                           float* __restrict__ Hnew, float* __restrict__ C, int H)
{
    int gid = blockIdx.x * 256 + threadIdx.x;     // over 32*H
    int m = gid / H, u = gid - m * H;
    float4 s = make_float4(0.f, 0.f, 0.f, 0.f);
    for (int ks = 0; ks < ksplit; ks++) {
        float4 p = *(const float4*)&pbuf[(size_t)(ks * 32 + m) * 4 * H + u * 4];
        s.x += p.x; s.y += p.y; s.z += p.z; s.w += p.w;
    }
    float iv = s.x + bih[u]         + bhh[u];
    float fv = s.y + bih[H + u]     + bhh[H + u];
    float gv = s.z + bih[2 * H + u] + bhh[2 * H + u];
    float ov = s.w + bih[3 * H + u] + bhh[3 * H + u];
    iv = 1.f / (1.f + expf(-iv));
    fv = 1.f / (1.f + expf(-fv));
    gv = tanhf(gv);
    ov = 1.f / (1.f + expf(-ov));
    float c = fv * C[gid] + iv * gv;
    C[gid]    = c;
    Hnew[gid] = ov * tanhf(c);
}

// ---------------- proj epilogue: sum partials + bias (+tanh) ----------------
template<int ACT>
__global__ void k_proj_epi(const float* __restrict__ pbuf, int ksplit,
                           const float* __restrict__ bias, float* __restrict__ out, int N)
{
    int gid = blockIdx.x * 256 + threadIdx.x;     // over 32*N/4
    int m = gid / (N / 4), nq = gid - m * (N / 4);
    float4 s = *(const float4*)&bias[nq * 4];
    for (int ks = 0; ks < ksplit; ks++) {
        float4 p = *(const float4*)&pbuf[(size_t)(ks * 32 + m) * N + nq * 4];
        s.x += p.x; s.y += p.y; s.z += p.z; s.w += p.w;
    }
    if (ACT == 1) { s.x = tanhf(s.x); s.y = tanhf(s.y); s.z = tanhf(s.z); s.w = tanhf(s.w); }
    *(float4*)&out[(size_t)m * N + nq * 4] = s;
}

// ---------------- small single-kernel proj (p2w, tiny) ----------------
template<int JT, int ACT>
__global__ void k_proj(const float* __restrict__ X, int K,
                       const float* __restrict__ W,
                       const float* __restrict__ bias,
                       float* __restrict__ out, int N)
{
    constexpr int OPT  = (32 * JT) / 256;
    constexpr int KQ   = 16;
    constexpr int LDS4 = 17;
    __shared__ float4 Xs[32 * LDS4];
    __shared__ float4 Ws[JT * LDS4];
    int tid = threadIdx.x;
    int jj  = tid % JT;
    int rg  = tid / JT;
    int j   = blockIdx.x * JT + jj;
    float b = bias ? bias[j] : 0.f;
    float acc[OPT];
#pragma unroll
    for (int i = 0; i < OPT; i++) acc[i] = b;
    for (int k0 = 0; k0 < K; k0 += 64) {
        for (int i = tid; i < 32 * KQ; i += 256) {
            int r = i >> 4, kq = i & 15;
            Xs[r * LDS4 + kq] = *(const float4*)(X + (size_t)r * K + k0 + kq * 4);
        }
        for (int i = tid; i < JT * KQ; i += 256) {
            int rr = i >> 4, kq = i & 15;
            Ws[rr * LDS4 + kq] =
                *(const float4*)(W + (size_t)(blockIdx.x * JT + rr) * K + k0 + kq * 4);
        }
        __syncthreads();
#pragma unroll
        for (int kq = 0; kq < KQ; kq++) {
            float4 wv = Ws[jj * LDS4 + kq];
#pragma unroll
            for (int i = 0; i < OPT; i++) {
                float4 xv = Xs[(rg * OPT + i) * LDS4 + kq];
                acc[i] = fmaf(xv.x, wv.x, acc[i]);
                acc[i] = fmaf(xv.y, wv.y, acc[i]);
                acc[i] = fmaf(xv.z, wv.z, acc[i]);
                acc[i] = fmaf(xv.w, wv.w, acc[i]);
            }
        }
        __syncthreads();
    }
#pragma unroll
    for (int i = 0; i < OPT; i++) {
        float v = acc[i];
        if (ACT == 1) v = tanhf(v);
        out[(size_t)(rg * OPT + i) * N + j] = v;
    }
}

// ---------------- pos head: logits + log_softmax (48-way) ----------------
__global__ void k_pos_out(const float* __restrict__ ph, const float* __restrict__ W,
                          const float* __restrict__ bias, float* __restrict__ out)
{
    int r = blockIdx.x;
    int j = threadIdx.x;
    __shared__ float vals[48];
    __shared__ float s_lse;
    float v = 0.f;
    if (j < 48) {
        v = bias[j];
        const float4* xp = (const float4*)(ph + r * 256);
        const float4* wp = (const float4*)(W + j * 256);
#pragma unroll 8
        for (int k = 0; k < 64; k++) {
            float4 x = xp[k], w = wp[k];
            v = fmaf(x.x, w.x, v); v = fmaf(x.y, w.y, v);
            v = fmaf(x.z, w.z, v); v = fmaf(x.w, w.w, v);
        }
        vals[j] = v;
    }
    __syncthreads();
    if (threadIdx.x == 0) {
        float m = -1e30f;
        for (int k = 0; k < 48; k++) m = fmaxf(m, vals[k]);
        float s = 0.f;
        for (int k = 0; k < 48; k++) s += expf(vals[k] - m);
        s_lse = m + logf(s);
    }
    __syncthreads();
    if (j < 48) out[r * 48 + j] = v - s_lse;
}

// ---------------- big final GEMM: out[2048,32000] = E[2048,512] @ W[32000,512]^T + b --
__global__ void k_big(const float* __restrict__ E, const float* __restrict__ W,
                      const float* __restrict__ bias, float* __restrict__ out)
{
    __shared__ float Es[16][68];
    __shared__ float Bs[16][68];
    int tid = threadIdx.x;
    int cg = tid % 16, rg = tid / 16;
    int mbase = blockIdx.y * 64, nbase = blockIdx.x * 64;

    float acc[4][4];
#pragma unroll
    for (int r = 0; r < 4; r++)
#pragma unroll
        for (int c = 0; c < 4; c++) acc[r][c] = 0.f;

    int ml = tid >> 2, kq = tid & 3;
    for (int k0 = 0; k0 < 512; k0 += 16) {
        float4 v = *(const float4*)(E + (size_t)(mbase + ml) * 512 + k0 + kq * 4);
        Es[kq*4+0][ml] = v.x; Es[kq*4+1][ml] = v.y;
        Es[kq*4+2][ml] = v.z; Es[kq*4+3][ml] = v.w;
        float4 w = *(const float4*)(W + (size_t)(nbase + ml) * 512 + k0 + kq * 4);
        Bs[kq*4+0][ml] = w.x; Bs[kq*4+1][ml] = w.y;
        Bs[kq*4+2][ml] = w.z; Bs[kq*4+3][ml] = w.w;
        __syncthreads();
#pragma unroll
        for (int k = 0; k < 16; k++) {
            float4 a = *(const float4*)&Es[k][rg * 4];
            float4 b = *(const float4*)&Bs[k][cg * 4];
            acc[0][0] = fmaf(a.x, b.x, acc[0][0]);
            acc[0][1] = fmaf(a.x, b.y, acc[0][1]);
            acc[0][2] = fmaf(a.x, b.z, acc[0][2]);
            acc[0][3] = fmaf(a.x, b.w, acc[0][3]);
            acc[1][0] = fmaf(a.y, b.x, acc[1][0]);
            acc[1][1] = fmaf(a.y, b.y, acc[1][1]);
            acc[1][2] = fmaf(a.y, b.z, acc[1][2]);
            acc[1][3] = fmaf(a.y, b.w, acc[1][3]);
            acc[2][0] = fmaf(a.z, b.x, acc[2][0]);
            acc[2][1] = fmaf(a.z, b.y, acc[2][1]);
            acc[2][2] = fmaf(a.z, b.z, acc[2][2]);
            acc[2][3] = fmaf(a.z, b.w, acc[2][3]);
            acc[3][0] = fmaf(a.w, b.x, acc[3][0]);
            acc[3][1] = fmaf(a.w, b.y, acc[3][1]);
            acc[3][2] = fmaf(a.w, b.z, acc[3][2]);
            acc[3][3] = fmaf(a.w, b.w, acc[3][3]);
        }
        __syncthreads();
    }
    float4 bv = *(const float4*)&bias[nbase + cg * 4];
#pragma unroll
    for (int r = 0; r < 4; r++) {
        float4 v = make_float4(acc[r][0] + bv.x, acc[r][1] + bv.y,
                               acc[r][2] + bv.z, acc[r][3] + bv.w);
        *(float4*)&out[(size_t)(mbase + rg * 4 + r) * WORD_V + nbase + cg * 4] = v;
    }
}

// ---------------- final word log_softmax over all T*B rows ----------------
__global__ void k_wnorm(float* __restrict__ wout)
{
    float* p = wout + (size_t)blockIdx.x * WORD_V;
    __shared__ float red[256];
    int tid = threadIdx.x;

    float m = -1e30f;
    for (int k = tid; k < WORD_V; k += 256) m = fmaxf(m, p[k]);
    red[tid] = m; __syncthreads();
    for (int s = 128; s > 0; s >>= 1) { if (tid < s) red[tid] = fmaxf(red[tid], red[tid + s]); __syncthreads(); }
    m = red[0]; __syncthreads();

    float s = 0.f;
    for (int k = tid; k < WORD_V; k += 256) s += expf(p[k] - m);
    red[tid] = s; __syncthreads();
    for (int st = 128; st > 0; st >>= 1) { if (tid < st) red[tid] += red[tid + st]; __syncthreads(); }
    float lse = m + logf(red[0]);

    for (int k = tid; k < WORD_V; k += 256) p[k] -= lse;
}

// ---------------- launch ----------------
extern "C" void kernel_launch(void* const* d_in, const int* in_sizes, int n_in,
                              void* d_out, int out_size)
{
    const int*   pos          = (const int*)  d_in[0];
    const int*   word         = (const int*)  d_in[1];
    const float* pos_emb_W    = (const float*)d_in[2];
    const float* word_emb_W   = (const float*)d_in[3];
    const float* w2p_W        = (const float*)d_in[4];
    const float* w2p_b        = (const float*)d_in[5];
    const float* p2w_W        = (const float*)d_in[6];
    const float* p2w_b        = (const float*)d_in[7];
    const float* p_Wih0       = (const float*)d_in[8];
    const float* p_Whh0       = (const float*)d_in[9];
    const float* p_bih0       = (const float*)d_in[10];
    const float* p_bhh0       = (const float*)d_in[11];
    const float* w_Wih0       = (const float*)d_in[12];
    const float* w_Whh0       = (const float*)d_in[13];
    const float* w_bih0       = (const float*)d_in[14];
    const float* w_bhh0       = (const float*)d_in[15];
    const float* w_Wih1       = (const float*)d_in[16];
    const float* w_Whh1       = (const float*)d_in[17];
    const float* w_bih1       = (const float*)d_in[18];
    const float* w_bhh1       = (const float*)d_in[19];
    const float* pos_proj_W   = (const float*)d_in[20];
    const float* pos_proj_b   = (const float*)d_in[21];
    const float* word_proj1_W = (const float*)d_in[22];
    const float* word_proj1_b = (const float*)d_in[23];
    const float* word_proj2_b = (const float*)d_in[24];

    float* scratch = nullptr;
    cudaGetSymbolAddress((void**)&scratch, g_scratch);

    float* ph[2]  = { scratch + OFF_PH0,  scratch + OFF_PH1  };
    float* pc     =   scratch + OFF_PC;
    float* wh0[2] = { scratch + OFF_WH0A, scratch + OFF_WH0B };
    float* wc0    =   scratch + OFF_WC0;
    float* wh1[2] = { scratch + OFF_WH1A, scratch + OFF_WH1B };
    float* wc1    =   scratch + OFF_WC1;
    float* lastw  =   scratch + OFF_LASTW;
    float* lastp  =   scratch + OFF_LASTP;
    float* ebuf   =   scratch + OFF_EBUF;
    float* pbuf   =   scratch + OFF_PBUF;

    float* pout = (float*)d_out;
    float* wout = pout + (size_t)TT * BATCH * POS_V;

    k_zero<<<STATE_TOTAL / 4 / 256, 256>>>(scratch);

    for (int t = 0; t < TT; t++) {
        int cur = t & 1, nxt = cur ^ 1;

        // last_w = tanh(w_h1_old @ w2p^T + b)   [K=1024, N=1024, split-4]
        k_gemm<64, false><<<dim3(16, 4), 128>>>(nullptr, wh1[cur], W_HID,
                                                nullptr, 0, nullptr, 0,
                                                w2p_W, nullptr, pbuf, 0, W_HID, 256);
        k_proj_epi<1><<<32, 256>>>(pbuf, 4, w2p_b, lastw, W_HID);

        // POS LSTM: x = [p_emb_t | last_w], h=ph  [K=1408, 4H=1024, split-4]
        k_gemm<64, true><<<dim3(16, 4), 128>>>(pos + t * BATCH, pos_emb_W, P_EMB,
                                               lastw, W_HID, ph[cur], P_HID,
                                               p_Wih0, p_Whh0, pbuf, P_HID, 4 * P_HID, 352);
        k_lstm_epi<<<32, 256>>>(pbuf, 4, p_bih0, p_bhh0, ph[nxt], pc, P_HID);

        // last_p = tanh(p_h_new @ p2w^T + b)  (tiny)
        k_proj<8, 1><<<P_HID / 8, 256>>>(ph[nxt], P_HID, p2w_W, p2w_b, lastp, P_HID);

        // pos logits + log_softmax
        k_pos_out<<<BATCH, 64>>>(ph[nxt], pos_proj_W, pos_proj_b,
                                 pout + (size_t)t * BATCH * POS_V);

        // word LSTM 0: x = [w_emb_t | last_p]  [K=1792, 4H=4096, split-2]
        k_gemm<64, true><<<dim3(64, 2), 128>>>(word + t * BATCH, word_emb_W, W_EMB,
                                               lastp, P_HID, wh0[cur], W_HID,
                                               w_Wih0, w_Whh0, pbuf, W_HID, 4 * W_HID, 896);
        k_lstm_epi<<<128, 256>>>(pbuf, 2, w_bih0, w_bhh0, wh0[nxt], wc0, W_HID);

        // word LSTM 1: x = w_h0_new  [K=2048, 4H=4096, split-2]
        k_gemm<64, true><<<dim3(64, 2), 128>>>(nullptr, wh0[nxt], W_HID,
                                               nullptr, 0, wh1[cur], W_HID,
                                               w_Wih1, w_Whh1, pbuf, W_HID, 4 * W_HID, 1024);
        k_lstm_epi<<<128, 256>>>(pbuf, 2, w_bih1, w_bhh1, wh1[nxt], wc1, W_HID);

        // e_t = w_h1_new @ proj1^T + b  [K=1024, N=512, split-4] -> stored for final GEMM
        k_gemm<64, false><<<dim3(8, 4), 128>>>(nullptr, wh1[nxt], W_HID,
                                               nullptr, 0, nullptr, 0,
                                               word_proj1_W, nullptr, pbuf, 0, W_EMB, 256);
        k_proj_epi<0><<<16, 256>>>(pbuf, 4, word_proj1_b, ebuf + (size_t)t * BATCH * W_EMB, W_EMB);
    }

    // ONE big word-logits GEMM over all timesteps, then log-softmax
    k_big<<<dim3(WORD_V / 64, (TT * BATCH) / 64), 256>>>(ebuf, word_emb_W, word_proj2_b, wout);
    k_wnorm<<<TT * BATCH, 256>>>(wout);
}